// round 1
// baseline (speedup 1.0000x reference)
#include <cuda_runtime.h>
#include <cuda_bf16.h>
#include <math.h>

#define HIDDEN    2048
#define NUM_HEADS 16
#define HEAD_DIM  128
#define WINDOW    256
#define BATCH     2
#define SEQ       2048
#define M_ROWS    (BATCH * SEQ)        // 4096

// -------- scratch (static device buffers; no allocation allowed) --------
__device__ float g_Q[BATCH * NUM_HEADS * SEQ * HEAD_DIM];   // 32MB
__device__ float g_K[BATCH * NUM_HEADS * SEQ * HEAD_DIM];
__device__ float g_V[BATCH * NUM_HEADS * SEQ * HEAD_DIM];
__device__ float g_AO[BATCH * SEQ * HIDDEN];                // attention output, [B,S,H*D]

// ======================= GEMM: C = A @ B + bias =======================
// A: [M,K] row-major, B: [K,N] row-major. BM=BN=128, BK=16, 256 thr, 8x8 microtile.
// HEAD_STORE=true scatters output into [B, H, S, D] layout (split heads).
#define BM 128
#define BN 128
#define BKK 16
#define TM 8
#define TN 8

template <bool HEAD_STORE>
__global__ __launch_bounds__(256) void gemm128(
    const float* __restrict__ A, const float* __restrict__ B,
    const float* __restrict__ bias, float* __restrict__ C,
    int M, int N, int K)
{
    __shared__ float As[BKK][BM];   // transposed: As[k][m]
    __shared__ float Bs[BKK][BN];   // Bs[k][n]

    const int tid = threadIdx.x;
    const int tx = tid & 15;        // 0..15
    const int ty = tid >> 4;        // 0..15
    const int m0 = blockIdx.y * BM;
    const int n0 = blockIdx.x * BN;

    float acc[TM][TN];
#pragma unroll
    for (int i = 0; i < TM; i++)
#pragma unroll
        for (int j = 0; j < TN; j++) acc[i][j] = 0.f;

    for (int k0 = 0; k0 < K; k0 += BKK) {
        // load A tile (128x16) transposed into As
#pragma unroll
        for (int it = 0; it < 2; it++) {
            int lin = tid + it * 256;            // 0..511
            int row = lin >> 2;                  // 0..127
            int c4  = (lin & 3) * 4;             // 0,4,8,12
            float4 v = *(const float4*)&A[(size_t)(m0 + row) * K + k0 + c4];
            As[c4 + 0][row] = v.x;
            As[c4 + 1][row] = v.y;
            As[c4 + 2][row] = v.z;
            As[c4 + 3][row] = v.w;
        }
        // load B tile (16x128)
#pragma unroll
        for (int it = 0; it < 2; it++) {
            int lin = tid + it * 256;
            int row = lin >> 5;                  // 0..15
            int c4  = (lin & 31) * 4;            // 0..124
            *(float4*)&Bs[row][c4] = *(const float4*)&B[(size_t)(k0 + row) * N + n0 + c4];
        }
        __syncthreads();

#pragma unroll
        for (int kk = 0; kk < BKK; kk++) {
            float a[TM], b[TN];
            *(float4*)&a[0] = *(const float4*)&As[kk][ty * TM];
            *(float4*)&a[4] = *(const float4*)&As[kk][ty * TM + 4];
            *(float4*)&b[0] = *(const float4*)&Bs[kk][tx * TN];
            *(float4*)&b[4] = *(const float4*)&Bs[kk][tx * TN + 4];
#pragma unroll
            for (int i = 0; i < TM; i++)
#pragma unroll
                for (int j = 0; j < TN; j++)
                    acc[i][j] += a[i] * b[j];
        }
        __syncthreads();
    }

    // epilogue
    float bn[TN];
#pragma unroll
    for (int j = 0; j < TN; j++) bn[j] = bias[n0 + tx * TN + j];

#pragma unroll
    for (int i = 0; i < TM; i++) {
        int m = m0 + ty * TM + i;
#pragma unroll
        for (int j = 0; j < TN; j++) {
            int n = n0 + tx * TN + j;
            float val = acc[i][j] + bn[j];
            if (HEAD_STORE) {
                int b  = m >> 11;          // m / SEQ
                int s  = m & (SEQ - 1);
                int h  = n >> 7;           // n / HEAD_DIM
                int d  = n & (HEAD_DIM - 1);
                C[((size_t)(b * NUM_HEADS + h) * SEQ + s) * HEAD_DIM + d] = val;
            } else {
                C[(size_t)m * N + n] = val;
            }
        }
    }
}

// ======================= RoPE (in-place on [B,H,S,D]) =======================
__global__ __launch_bounds__(256) void rope_kernel(float* __restrict__ T)
{
    int idx = blockIdx.x * blockDim.x + threadIdx.x;   // B*H*S*64 threads
    int d   = idx & 63;
    int row = idx >> 6;
    int s   = row & (SEQ - 1);

    float inv = powf(10000.0f, -(float)(2 * d) / (float)HEAD_DIM);
    float fr  = (float)s * inv;
    float c, sn;
    sincosf(fr, &sn, &c);

    float* p = T + (size_t)row * HEAD_DIM;
    float t1 = p[d];
    float t2 = p[d + 64];
    p[d]      = t1 * c - t2 * sn;
    p[d + 64] = t1 * sn + t2 * c;
}

// ======================= Sliding-window attention =======================
// Block: 256 threads, one (b,h, 64-query tile). Streams 64-key chunks,
// online softmax. Q/K transposed in smem for conflict-free score GEMM.
#define QT 64
// dynamic smem layout (floats):
//   Qst [128][64]   : 8192
//   Kst [128][64]   : 8192
//   Vs  [64][128]   : 8192
//   Ss  [64][65]    : 4160
#define SM_QST 0
#define SM_KST 8192
#define SM_VS  16384
#define SM_SS  24576
#define SM_TOTAL_F (24576 + 64 * 65)
#define SM_ATTN_BYTES (SM_TOTAL_F * 4)

__global__ __launch_bounds__(256) void swattn_kernel(
    const float* __restrict__ Q, const float* __restrict__ K,
    const float* __restrict__ V, const float* __restrict__ kw,
    float* __restrict__ AO)
{
    extern __shared__ float sm[];
    float* Qst = sm + SM_QST;   // [d][q], stride 64
    float* Kst = sm + SM_KST;   // [d][k], stride 64
    float* Vs  = sm + SM_VS;    // [k][d], stride 128
    float* Ss  = sm + SM_SS;    // [q][k], stride 65

    const int tid = threadIdx.x;
    const int bh  = blockIdx.y;             // b*16 + h
    const int h   = bh & (NUM_HEADS - 1);
    const int b   = bh >> 4;
    const int q0  = blockIdx.x * QT;

    const float qscale = kw[h] * rsqrtf((float)HEAD_DIM);

    const float* Qb = Q + (size_t)bh * SEQ * HEAD_DIM;
    const float* Kb = K + (size_t)bh * SEQ * HEAD_DIM;
    const float* Vb = V + (size_t)bh * SEQ * HEAD_DIM;

    // load Q tile, scaled, transposed
#pragma unroll
    for (int it = 0; it < 8; it++) {
        int lin = tid + it * 256;           // 0..2047
        int q   = lin >> 5;                 // 0..63
        int d4  = (lin & 31) * 4;
        float4 v = *(const float4*)&Qb[(size_t)(q0 + q) * HEAD_DIM + d4];
        Qst[(d4 + 0) * 64 + q] = v.x * qscale;
        Qst[(d4 + 1) * 64 + q] = v.y * qscale;
        Qst[(d4 + 2) * 64 + q] = v.z * qscale;
        Qst[(d4 + 3) * 64 + q] = v.w * qscale;
    }

    // per-thread softmax/output state: row r = tid/4, lane group g = tid%4
    const int r = tid >> 2;
    const int g = tid & 3;
    float mrow = -1e30f;
    float lrow = 0.f;
    float4 acc4[8];
#pragma unroll
    for (int t = 0; t < 8; t++) acc4[t] = make_float4(0.f, 0.f, 0.f, 0.f);

    const int txx = tid & 15;
    const int tyy = tid >> 4;

    int c_start = q0 - WINDOW; if (c_start < 0) c_start = 0;

    for (int k0 = c_start; k0 <= q0; k0 += QT) {
        __syncthreads();   // previous chunk's AV done; Q load visible (first iter)

        // load K chunk (transposed) + V chunk
#pragma unroll
        for (int it = 0; it < 8; it++) {
            int lin = tid + it * 256;
            int kq  = lin >> 5;
            int d4  = (lin & 31) * 4;
            float4 kv = *(const float4*)&Kb[(size_t)(k0 + kq) * HEAD_DIM + d4];
            Kst[(d4 + 0) * 64 + kq] = kv.x;
            Kst[(d4 + 1) * 64 + kq] = kv.y;
            Kst[(d4 + 2) * 64 + kq] = kv.z;
            Kst[(d4 + 3) * 64 + kq] = kv.w;
            *(float4*)&Vs[kq * HEAD_DIM + d4] =
                *(const float4*)&Vb[(size_t)(k0 + kq) * HEAD_DIM + d4];
        }
        __syncthreads();

        // scores: 16x16 threads, 4x4 microtile over [64q x 64k]
        float sc[4][4];
#pragma unroll
        for (int i = 0; i < 4; i++)
#pragma unroll
            for (int j = 0; j < 4; j++) sc[i][j] = 0.f;

        for (int d = 0; d < HEAD_DIM; d++) {
            float4 a = *(const float4*)&Qst[d * 64 + tyy * 4];
            float4 bb = *(const float4*)&Kst[d * 64 + txx * 4];
            sc[0][0] += a.x * bb.x; sc[0][1] += a.x * bb.y; sc[0][2] += a.x * bb.z; sc[0][3] += a.x * bb.w;
            sc[1][0] += a.y * bb.x; sc[1][1] += a.y * bb.y; sc[1][2] += a.y * bb.z; sc[1][3] += a.y * bb.w;
            sc[2][0] += a.z * bb.x; sc[2][1] += a.z * bb.y; sc[2][2] += a.z * bb.z; sc[2][3] += a.z * bb.w;
            sc[3][0] += a.w * bb.x; sc[3][1] += a.w * bb.y; sc[3][2] += a.w * bb.z; sc[3][3] += a.w * bb.w;
        }
        // mask + store scores
#pragma unroll
        for (int i = 0; i < 4; i++) {
            int qg = q0 + tyy * 4 + i;
#pragma unroll
            for (int j = 0; j < 4; j++) {
                int kg = k0 + txx * 4 + j;
                bool ok = (kg <= qg) && (kg >= qg - WINDOW);
                Ss[(tyy * 4 + i) * 65 + (txx * 4 + j)] = ok ? sc[i][j] : -1e30f;
            }
        }
        __syncthreads();

        // online softmax for row r, thread g scans j in [g*16, g*16+16)
        float cmax = -1e30f;
#pragma unroll
        for (int j = 0; j < 16; j++)
            cmax = fmaxf(cmax, Ss[r * 65 + g * 16 + j]);
        cmax = fmaxf(cmax, __shfl_xor_sync(0xffffffffu, cmax, 1));
        cmax = fmaxf(cmax, __shfl_xor_sync(0xffffffffu, cmax, 2));

        float newm = fmaxf(mrow, cmax);
        float rescale = expf(mrow - newm);

        float psum = 0.f;
#pragma unroll
        for (int j = 0; j < 16; j++) {
            float p = expf(Ss[r * 65 + g * 16 + j] - newm);
            Ss[r * 65 + g * 16 + j] = p;
            psum += p;
        }
        psum += __shfl_xor_sync(0xffffffffu, psum, 1);
        psum += __shfl_xor_sync(0xffffffffu, psum, 2);
        lrow = lrow * rescale + psum;
        mrow = newm;
        __syncwarp();

#pragma unroll
        for (int t = 0; t < 8; t++) {
            acc4[t].x *= rescale; acc4[t].y *= rescale;
            acc4[t].z *= rescale; acc4[t].w *= rescale;
        }
        // AV: thread g owns d = g*4 + 16*t + e  (conflict-free broadcast reads)
        for (int j = 0; j < QT; j++) {
            float p = Ss[r * 65 + j];
#pragma unroll
            for (int t = 0; t < 8; t++) {
                float4 v = *(const float4*)&Vs[j * HEAD_DIM + g * 4 + t * 16];
                acc4[t].x += p * v.x;
                acc4[t].y += p * v.y;
                acc4[t].z += p * v.z;
                acc4[t].w += p * v.w;
            }
        }
    }

    // write output row to [B, S, H*D]
    float invl = 1.0f / lrow;
    float* op = AO + ((size_t)b * SEQ + q0 + r) * HIDDEN + h * HEAD_DIM + g * 4;
#pragma unroll
    for (int t = 0; t < 8; t++) {
        float4 v;
        v.x = acc4[t].x * invl; v.y = acc4[t].y * invl;
        v.z = acc4[t].z * invl; v.w = acc4[t].w * invl;
        *(float4*)&op[t * 16] = v;
    }
}

// ======================= launch =======================
extern "C" void kernel_launch(void* const* d_in, const int* in_sizes, int n_in,
                              void* d_out, int out_size)
{
    const float* x   = (const float*)d_in[0];
    const float* W_Q = (const float*)d_in[1];
    const float* b_Q = (const float*)d_in[2];
    const float* W_K = (const float*)d_in[3];
    const float* b_K = (const float*)d_in[4];
    const float* W_V = (const float*)d_in[5];
    const float* b_V = (const float*)d_in[6];
    const float* W_O = (const float*)d_in[7];
    const float* b_O = (const float*)d_in[8];
    const float* kw  = (const float*)d_in[9];

    float *Q, *K, *V, *AO;
    cudaGetSymbolAddress((void**)&Q,  g_Q);
    cudaGetSymbolAddress((void**)&K,  g_K);
    cudaGetSymbolAddress((void**)&V,  g_V);
    cudaGetSymbolAddress((void**)&AO, g_AO);

    dim3 gg(HIDDEN / BN, M_ROWS / BM);   // (16, 32)
    gemm128<true><<<gg, 256>>>(x, W_Q, b_Q, Q, M_ROWS, HIDDEN, HIDDEN);
    gemm128<true><<<gg, 256>>>(x, W_K, b_K, K, M_ROWS, HIDDEN, HIDDEN);
    gemm128<true><<<gg, 256>>>(x, W_V, b_V, V, M_ROWS, HIDDEN, HIDDEN);

    int ropeThreads = BATCH * NUM_HEADS * SEQ * 64;
    rope_kernel<<<ropeThreads / 256, 256>>>(Q);
    rope_kernel<<<ropeThreads / 256, 256>>>(K);

    cudaFuncSetAttribute(swattn_kernel,
                         cudaFuncAttributeMaxDynamicSharedMemorySize, SM_ATTN_BYTES);
    dim3 ga(SEQ / QT, BATCH * NUM_HEADS);
    swattn_kernel<<<ga, 256, SM_ATTN_BYTES>>>(Q, K, V, kw, AO);

    gemm128<false><<<gg, 256>>>(AO, W_O, b_O, (float*)d_out, M_ROWS, HIDDEN, HIDDEN);
}

// round 2
// speedup vs baseline: 2.4213x; 2.4213x over previous
#include <cuda_runtime.h>
#include <cuda_bf16.h>
#include <math.h>
#include <stdint.h>

#define HIDDEN    2048
#define NUM_HEADS 16
#define HEAD_DIM  128
#define WINDOW    256
#define BATCH     2
#define SEQ       2048
#define M_ROWS    (BATCH * SEQ)        // 4096

// -------- scratch (static device buffers; no allocation allowed) --------
__device__ float g_Q[BATCH * NUM_HEADS * SEQ * HEAD_DIM];   // 32MB
__device__ float g_K[BATCH * NUM_HEADS * SEQ * HEAD_DIM];
__device__ float g_V[BATCH * NUM_HEADS * SEQ * HEAD_DIM];
__device__ float g_AO[BATCH * SEQ * HIDDEN];                // attention output, [B,S,H*D]

// ======================= TF32 tensor-core GEMM =======================
// C = A @ B + bias.  A: [M,K] row-major, B: [K,N] row-major.
// BM=BN=128, BK=16. 256 threads = 8 warps (2 warps M x 4 warps N),
// warp tile 64x32 = 4x4 grid of m16n8k8 mma. cp.async double buffer.
#define BM 128
#define BN 128
#define BKT 16
#define AST 20     // As row stride in floats ([m][k] layout, pad 4 -> conflict-free frags)
#define BST 136    // Bs row stride in floats ([k][n] layout, pad 8 -> conflict-free frags)

__device__ __forceinline__ uint32_t f2tf32(float f) {
    uint32_t r;
    asm("cvt.rna.tf32.f32 %0, %1;" : "=r"(r) : "f"(f));
    return r;
}

__device__ __forceinline__ void cp_async16(uint32_t smem_addr, const void* gptr) {
    asm volatile("cp.async.cg.shared.global [%0], [%1], 16;\n"
                 :: "r"(smem_addr), "l"(gptr));
}
__device__ __forceinline__ void cp_commit() {
    asm volatile("cp.async.commit_group;\n" ::: "memory");
}
__device__ __forceinline__ void cp_wait1() {
    asm volatile("cp.async.wait_group 1;\n" ::: "memory");
}

__device__ __forceinline__ void mma_tf32(
    float& c0, float& c1, float& c2, float& c3,
    uint32_t a0, uint32_t a1, uint32_t a2, uint32_t a3,
    uint32_t b0, uint32_t b1)
{
    asm volatile(
        "mma.sync.aligned.m16n8k8.row.col.f32.tf32.tf32.f32 "
        "{%0,%1,%2,%3},{%4,%5,%6,%7},{%8,%9},{%0,%1,%2,%3};"
        : "+f"(c0), "+f"(c1), "+f"(c2), "+f"(c3)
        : "r"(a0), "r"(a1), "r"(a2), "r"(a3), "r"(b0), "r"(b1));
}

template <bool HEAD_STORE>
__global__ __launch_bounds__(256) void gemm_tf32(
    const float* __restrict__ A, const float* __restrict__ B,
    const float* __restrict__ bias, float* __restrict__ C,
    int M, int N, int K)
{
    __shared__ float As[2][BM][AST];    // [m][k]
    __shared__ float Bs[2][BKT][BST];   // [k][n]

    const int tid  = threadIdx.x;
    const int lane = tid & 31;
    const int warp = tid >> 5;
    const int wm   = warp >> 2;          // 0..1 (M)
    const int wn   = warp & 3;           // 0..3 (N)
    const int g    = lane >> 2;          // 0..7
    const int t    = lane & 3;           // 0..3
    const int m0   = blockIdx.y * BM;
    const int n0   = blockIdx.x * BN;

    // load indices (2 x 16B per thread per tile)
    const int a_row0 = (tid + 0)   >> 2;        // 0..63
    const int a_row1 = (tid + 256) >> 2;        // 64..127
    const int a_seg  = (tid & 3) * 4;
    const int b_row0 = (tid + 0)   >> 5;        // 0..7
    const int b_row1 = (tid + 256) >> 5;        // 8..15
    const int b_seg  = (tid & 31) * 4;

    float acc[4][4][4];
#pragma unroll
    for (int i = 0; i < 4; i++)
#pragma unroll
        for (int j = 0; j < 4; j++)
#pragma unroll
            for (int e = 0; e < 4; e++) acc[i][j][e] = 0.f;

    auto load_stage = [&](int st, int k0) {
        uint32_t asm0 = (uint32_t)__cvta_generic_to_shared(&As[st][a_row0][a_seg]);
        uint32_t asm1 = (uint32_t)__cvta_generic_to_shared(&As[st][a_row1][a_seg]);
        cp_async16(asm0, &A[(size_t)(m0 + a_row0) * K + k0 + a_seg]);
        cp_async16(asm1, &A[(size_t)(m0 + a_row1) * K + k0 + a_seg]);
        uint32_t bsm0 = (uint32_t)__cvta_generic_to_shared(&Bs[st][b_row0][b_seg]);
        uint32_t bsm1 = (uint32_t)__cvta_generic_to_shared(&Bs[st][b_row1][b_seg]);
        cp_async16(bsm0, &B[(size_t)(k0 + b_row0) * N + n0 + b_seg]);
        cp_async16(bsm1, &B[(size_t)(k0 + b_row1) * N + n0 + b_seg]);
    };

    const int niter = K / BKT;   // 128
    load_stage(0, 0);
    cp_commit();

    for (int iter = 0; iter < niter; iter++) {
        const int buf = iter & 1;
        if (iter + 1 < niter) load_stage(buf ^ 1, (iter + 1) * BKT);
        cp_commit();
        cp_wait1();
        __syncthreads();

        const float (*as)[AST] = As[buf];
        const float (*bs)[BST] = Bs[buf];

#pragma unroll
        for (int ks = 0; ks < 2; ks++) {
            const int kk = ks * 8;
            uint32_t af[4][4], bf[4][2];
#pragma unroll
            for (int mf = 0; mf < 4; mf++) {
                int mr = wm * 64 + mf * 16 + g;
                af[mf][0] = f2tf32(as[mr    ][kk + t]);
                af[mf][1] = f2tf32(as[mr + 8][kk + t]);
                af[mf][2] = f2tf32(as[mr    ][kk + t + 4]);
                af[mf][3] = f2tf32(as[mr + 8][kk + t + 4]);
            }
#pragma unroll
            for (int nf = 0; nf < 4; nf++) {
                int nc = wn * 32 + nf * 8 + g;
                bf[nf][0] = f2tf32(bs[kk + t    ][nc]);
                bf[nf][1] = f2tf32(bs[kk + t + 4][nc]);
            }
#pragma unroll
            for (int mf = 0; mf < 4; mf++)
#pragma unroll
                for (int nf = 0; nf < 4; nf++)
                    mma_tf32(acc[mf][nf][0], acc[mf][nf][1], acc[mf][nf][2], acc[mf][nf][3],
                             af[mf][0], af[mf][1], af[mf][2], af[mf][3],
                             bf[nf][0], bf[nf][1]);
        }
        __syncthreads();
    }

    // epilogue: c0->(r,c) c1->(r,c+1) c2->(r+8,c) c3->(r+8,c+1)
#pragma unroll
    for (int mf = 0; mf < 4; mf++) {
        int row0 = m0 + wm * 64 + mf * 16 + g;
#pragma unroll
        for (int nf = 0; nf < 4; nf++) {
            int col = n0 + wn * 32 + nf * 8 + 2 * t;
            float b0 = bias[col], b1 = bias[col + 1];
            float v00 = acc[mf][nf][0] + b0, v01 = acc[mf][nf][1] + b1;
            float v10 = acc[mf][nf][2] + b0, v11 = acc[mf][nf][3] + b1;
            if (HEAD_STORE) {
                int bi = row0 >> 11, s = row0 & (SEQ - 1);
                int h  = col >> 7,  d = col & (HEAD_DIM - 1);
                float* p0 = &g_Q[0]; // placeholder to silence unused warn path
                (void)p0;
                size_t base0 = ((size_t)(bi * NUM_HEADS + h) * SEQ + s) * HEAD_DIM + d;
                *(float2*)&C[base0] = make_float2(v00, v01);
                int row1 = row0 + 8;
                int s1 = row1 & (SEQ - 1); int bi1 = row1 >> 11;
                size_t base1 = ((size_t)(bi1 * NUM_HEADS + h) * SEQ + s1) * HEAD_DIM + d;
                *(float2*)&C[base1] = make_float2(v10, v11);
            } else {
                *(float2*)&C[(size_t)row0 * N + col]       = make_float2(v00, v01);
                *(float2*)&C[(size_t)(row0 + 8) * N + col] = make_float2(v10, v11);
            }
        }
    }
}

// ======================= RoPE (in-place on [B,H,S,D]) =======================
__global__ __launch_bounds__(256) void rope_kernel(float* __restrict__ T)
{
    int idx = blockIdx.x * blockDim.x + threadIdx.x;   // B*H*S*64 threads
    int d   = idx & 63;
    int row = idx >> 6;
    int s   = row & (SEQ - 1);

    float inv = powf(10000.0f, -(float)(2 * d) / (float)HEAD_DIM);
    float fr  = (float)s * inv;
    float c, sn;
    sincosf(fr, &sn, &c);

    float* p = T + (size_t)row * HEAD_DIM;
    float t1 = p[d];
    float t2 = p[d + 64];
    p[d]      = t1 * c - t2 * sn;
    p[d + 64] = t1 * sn + t2 * c;
}

// ======================= Sliding-window attention =======================
#define QT 64
#define SM_QST 0
#define SM_KST 8192
#define SM_VS  16384
#define SM_SS  24576
#define SM_TOTAL_F (24576 + 64 * 65)
#define SM_ATTN_BYTES (SM_TOTAL_F * 4)

__global__ __launch_bounds__(256) void swattn_kernel(
    const float* __restrict__ Q, const float* __restrict__ K,
    const float* __restrict__ V, const float* __restrict__ kw,
    float* __restrict__ AO)
{
    extern __shared__ float sm[];
    float* Qst = sm + SM_QST;   // [d][q], stride 64
    float* Kst = sm + SM_KST;   // [d][k], stride 64
    float* Vs  = sm + SM_VS;    // [k][d], stride 128
    float* Ss  = sm + SM_SS;    // [q][k], stride 65

    const int tid = threadIdx.x;
    const int bh  = blockIdx.y;             // b*16 + h
    const int h   = bh & (NUM_HEADS - 1);
    const int b   = bh >> 4;
    const int q0  = blockIdx.x * QT;

    const float qscale = kw[h] * rsqrtf((float)HEAD_DIM);

    const float* Qb = Q + (size_t)bh * SEQ * HEAD_DIM;
    const float* Kb = K + (size_t)bh * SEQ * HEAD_DIM;
    const float* Vb = V + (size_t)bh * SEQ * HEAD_DIM;

#pragma unroll
    for (int it = 0; it < 8; it++) {
        int lin = tid + it * 256;
        int q   = lin >> 5;
        int d4  = (lin & 31) * 4;
        float4 v = *(const float4*)&Qb[(size_t)(q0 + q) * HEAD_DIM + d4];
        Qst[(d4 + 0) * 64 + q] = v.x * qscale;
        Qst[(d4 + 1) * 64 + q] = v.y * qscale;
        Qst[(d4 + 2) * 64 + q] = v.z * qscale;
        Qst[(d4 + 3) * 64 + q] = v.w * qscale;
    }

    const int r = tid >> 2;
    const int g = tid & 3;
    float mrow = -1e30f;
    float lrow = 0.f;
    float4 acc4[8];
#pragma unroll
    for (int t = 0; t < 8; t++) acc4[t] = make_float4(0.f, 0.f, 0.f, 0.f);

    const int txx = tid & 15;
    const int tyy = tid >> 4;

    int c_start = q0 - WINDOW; if (c_start < 0) c_start = 0;

    for (int k0 = c_start; k0 <= q0; k0 += QT) {
        __syncthreads();

#pragma unroll
        for (int it = 0; it < 8; it++) {
            int lin = tid + it * 256;
            int kq  = lin >> 5;
            int d4  = (lin & 31) * 4;
            float4 kv = *(const float4*)&Kb[(size_t)(k0 + kq) * HEAD_DIM + d4];
            Kst[(d4 + 0) * 64 + kq] = kv.x;
            Kst[(d4 + 1) * 64 + kq] = kv.y;
            Kst[(d4 + 2) * 64 + kq] = kv.z;
            Kst[(d4 + 3) * 64 + kq] = kv.w;
            *(float4*)&Vs[kq * HEAD_DIM + d4] =
                *(const float4*)&Vb[(size_t)(k0 + kq) * HEAD_DIM + d4];
        }
        __syncthreads();

        float sc[4][4];
#pragma unroll
        for (int i = 0; i < 4; i++)
#pragma unroll
            for (int j = 0; j < 4; j++) sc[i][j] = 0.f;

        for (int d = 0; d < HEAD_DIM; d++) {
            float4 a  = *(const float4*)&Qst[d * 64 + tyy * 4];
            float4 bb = *(const float4*)&Kst[d * 64 + txx * 4];
            sc[0][0] += a.x * bb.x; sc[0][1] += a.x * bb.y; sc[0][2] += a.x * bb.z; sc[0][3] += a.x * bb.w;
            sc[1][0] += a.y * bb.x; sc[1][1] += a.y * bb.y; sc[1][2] += a.y * bb.z; sc[1][3] += a.y * bb.w;
            sc[2][0] += a.z * bb.x; sc[2][1] += a.z * bb.y; sc[2][2] += a.z * bb.z; sc[2][3] += a.z * bb.w;
            sc[3][0] += a.w * bb.x; sc[3][1] += a.w * bb.y; sc[3][2] += a.w * bb.z; sc[3][3] += a.w * bb.w;
        }
#pragma unroll
        for (int i = 0; i < 4; i++) {
            int qg = q0 + tyy * 4 + i;
#pragma unroll
            for (int j = 0; j < 4; j++) {
                int kg = k0 + txx * 4 + j;
                bool ok = (kg <= qg) && (kg >= qg - WINDOW);
                Ss[(tyy * 4 + i) * 65 + (txx * 4 + j)] = ok ? sc[i][j] : -1e30f;
            }
        }
        __syncthreads();

        float cmax = -1e30f;
#pragma unroll
        for (int j = 0; j < 16; j++)
            cmax = fmaxf(cmax, Ss[r * 65 + g * 16 + j]);
        cmax = fmaxf(cmax, __shfl_xor_sync(0xffffffffu, cmax, 1));
        cmax = fmaxf(cmax, __shfl_xor_sync(0xffffffffu, cmax, 2));

        float newm = fmaxf(mrow, cmax);
        float rescale = expf(mrow - newm);

        float psum = 0.f;
#pragma unroll
        for (int j = 0; j < 16; j++) {
            float p = expf(Ss[r * 65 + g * 16 + j] - newm);
            Ss[r * 65 + g * 16 + j] = p;
            psum += p;
        }
        psum += __shfl_xor_sync(0xffffffffu, psum, 1);
        psum += __shfl_xor_sync(0xffffffffu, psum, 2);
        lrow = lrow * rescale + psum;
        mrow = newm;
        __syncwarp();

#pragma unroll
        for (int t = 0; t < 8; t++) {
            acc4[t].x *= rescale; acc4[t].y *= rescale;
            acc4[t].z *= rescale; acc4[t].w *= rescale;
        }
        for (int j = 0; j < QT; j++) {
            float p = Ss[r * 65 + j];
#pragma unroll
            for (int t = 0; t < 8; t++) {
                float4 v = *(const float4*)&Vs[j * HEAD_DIM + g * 4 + t * 16];
                acc4[t].x += p * v.x;
                acc4[t].y += p * v.y;
                acc4[t].z += p * v.z;
                acc4[t].w += p * v.w;
            }
        }
    }

    float invl = 1.0f / lrow;
    float* op = AO + ((size_t)b * SEQ + q0 + r) * HIDDEN + h * HEAD_DIM + g * 4;
#pragma unroll
    for (int t = 0; t < 8; t++) {
        float4 v;
        v.x = acc4[t].x * invl; v.y = acc4[t].y * invl;
        v.z = acc4[t].z * invl; v.w = acc4[t].w * invl;
        *(float4*)&op[t * 16] = v;
    }
}

// ======================= launch =======================
extern "C" void kernel_launch(void* const* d_in, const int* in_sizes, int n_in,
                              void* d_out, int out_size)
{
    const float* x   = (const float*)d_in[0];
    const float* W_Q = (const float*)d_in[1];
    const float* b_Q = (const float*)d_in[2];
    const float* W_K = (const float*)d_in[3];
    const float* b_K = (const float*)d_in[4];
    const float* W_V = (const float*)d_in[5];
    const float* b_V = (const float*)d_in[6];
    const float* W_O = (const float*)d_in[7];
    const float* b_O = (const float*)d_in[8];
    const float* kw  = (const float*)d_in[9];

    float *Q, *K, *V, *AO;
    cudaGetSymbolAddress((void**)&Q,  g_Q);
    cudaGetSymbolAddress((void**)&K,  g_K);
    cudaGetSymbolAddress((void**)&V,  g_V);
    cudaGetSymbolAddress((void**)&AO, g_AO);

    dim3 gg(HIDDEN / BN, M_ROWS / BM);   // (16, 32)
    gemm_tf32<true><<<gg, 256>>>(x, W_Q, b_Q, Q, M_ROWS, HIDDEN, HIDDEN);
    gemm_tf32<true><<<gg, 256>>>(x, W_K, b_K, K, M_ROWS, HIDDEN, HIDDEN);
    gemm_tf32<true><<<gg, 256>>>(x, W_V, b_V, V, M_ROWS, HIDDEN, HIDDEN);

    int ropeThreads = BATCH * NUM_HEADS * SEQ * 64;
    rope_kernel<<<ropeThreads / 256, 256>>>(Q);
    rope_kernel<<<ropeThreads / 256, 256>>>(K);

    cudaFuncSetAttribute(swattn_kernel,
                         cudaFuncAttributeMaxDynamicSharedMemorySize, SM_ATTN_BYTES);
    dim3 ga(SEQ / QT, BATCH * NUM_HEADS);
    swattn_kernel<<<ga, 256, SM_ATTN_BYTES>>>(Q, K, V, kw, AO);

    gemm_tf32<false><<<gg, 256>>>(AO, W_O, b_O, (float*)d_out, M_ROWS, HIDDEN, HIDDEN);
}